// round 3
// baseline (speedup 1.0000x reference)
#include <cuda_runtime.h>
#include <math.h>

#define EMB   1024
#define HS    64
#define TSEQ  4096
#define BATCH 4
#define MTOT  (BATCH * TSEQ)   // 16384 rows

// Scratch for Q, K, V projections (device globals: allocation-free rule)
__device__ float g_q[MTOT * HS];
__device__ float g_k[MTOT * HS];
__device__ float g_v[MTOT * HS];

// ---------------------------------------------------------------------------
// Kernel 1: QKV projection.  Y = X @ W for W in {Wq, Wk, Wv} (blockIdx.y).
// BM=128, BN=64(=HS), BK=16. 256 threads, each computes an 8x4 microtile.
// ---------------------------------------------------------------------------
__global__ __launch_bounds__(256) void qkv_kernel(
    const float* __restrict__ X,
    const float* __restrict__ Wq,
    const float* __restrict__ Wk,
    const float* __restrict__ Wv)
{
    __shared__ float Xs[16][128];   // transposed: Xs[k][row]
    __shared__ float Ws[16][64];    // natural:    Ws[k][col]

    const float* W;
    float* Y;
    if (blockIdx.y == 0)      { W = Wq; Y = g_q; }
    else if (blockIdx.y == 1) { W = Wk; Y = g_k; }
    else                      { W = Wv; Y = g_v; }

    const int tid = threadIdx.x;
    const int tx = tid & 15;        // 0..15 -> cols 4*tx
    const int ty = tid >> 4;        // 0..15 -> rows 8*ty
    const int m0 = blockIdx.x * 128;

    const int lr = tid & 127;       // load row for X tile
    const int lc = tid >> 7;        // 0/1 -> float4 chunks {lc, lc+2}
    const int wr = tid >> 4;        // W tile row 0..15
    const int wc = (tid & 15) * 4;  // W tile col

    float acc[8][4];
#pragma unroll
    for (int i = 0; i < 8; i++)
#pragma unroll
        for (int j = 0; j < 4; j++) acc[i][j] = 0.0f;

    for (int k0 = 0; k0 < EMB; k0 += 16) {
        // X tile (128x16), stored transposed
#pragma unroll
        for (int t = 0; t < 2; t++) {
            int c4 = lc + 2 * t;    // 0..3
            float4 xv = *(const float4*)&X[(size_t)(m0 + lr) * EMB + k0 + 4 * c4];
            Xs[4 * c4 + 0][lr] = xv.x;
            Xs[4 * c4 + 1][lr] = xv.y;
            Xs[4 * c4 + 2][lr] = xv.z;
            Xs[4 * c4 + 3][lr] = xv.w;
        }
        // W tile (16x64)
        *(float4*)&Ws[wr][wc] = *(const float4*)&W[(size_t)(k0 + wr) * HS + wc];
        __syncthreads();

#pragma unroll
        for (int kk = 0; kk < 16; kk++) {
            float4 a0 = *(const float4*)&Xs[kk][8 * ty];
            float4 a1 = *(const float4*)&Xs[kk][8 * ty + 4];
            float4 bv = *(const float4*)&Ws[kk][4 * tx];
            float a[8] = {a0.x, a0.y, a0.z, a0.w, a1.x, a1.y, a1.z, a1.w};
            float bb[4] = {bv.x, bv.y, bv.z, bv.w};
#pragma unroll
            for (int i = 0; i < 8; i++)
#pragma unroll
                for (int j = 0; j < 4; j++)
                    acc[i][j] = fmaf(a[i], bb[j], acc[i][j]);
        }
        __syncthreads();
    }

#pragma unroll
    for (int i = 0; i < 8; i++) {
        float4 o = make_float4(acc[i][0], acc[i][1], acc[i][2], acc[i][3]);
        *(float4*)&Y[(size_t)(m0 + 8 * ty + i) * HS + 4 * tx] = o;
    }
}

// ---------------------------------------------------------------------------
// Kernel 2: causal flash attention, fp32, 64x64 tiles.
// Grid: (64 q-tiles, 4 batches); qt = 63 - blockIdx.x so the expensive
// (long-causal-span) blocks launch first for load balance.
// 256 threads = 16x16 grid; each thread owns a 4x4 microtile.
// smem strides: 68 (=64+4) so stride-scalar reads are bank-conflict free,
// still 16B-aligned for float4.
// ---------------------------------------------------------------------------
#define QSTRIDE 68
#define SMEM_FLOATS (64 * QSTRIDE /*Qs*/ + 64 * 64 /*Kst*/ + 64 * QSTRIDE /*Vs*/ + 64 * QSTRIDE /*Ps*/)
#define SMEM_BYTES (SMEM_FLOATS * 4)

__global__ __launch_bounds__(256) void attn_kernel(float* __restrict__ out)
{
    extern __shared__ float sm[];
    float* Qs  = sm;                       // [64][68] natural
    float* Kst = Qs  + 64 * QSTRIDE;       // [64][64] transposed: Kst[h][j]
    float* Vs  = Kst + 64 * 64;            // [64][68] natural
    float* Ps  = Vs  + 64 * QSTRIDE;       // [64][68] natural

    const int b  = blockIdx.y;
    const int qt = 63 - (int)blockIdx.x;   // big blocks first
    const int tid = threadIdx.x;
    const int tx = tid & 15;
    const int ty = tid >> 4;

    const float* Qg = g_q + ((size_t)b * TSEQ + qt * 64) * HS;
    const float* Kg = g_k + (size_t)b * TSEQ * HS;
    const float* Vg = g_v + (size_t)b * TSEQ * HS;

    // ---- load Q tile (once) ----
    {
        int r  = tid & 63;
        int cb = tid >> 6;                 // 0..3
#pragma unroll
        for (int t = 0; t < 4; t++) {
            int c4 = cb + 4 * t;           // 0..15
            float4 v = *(const float4*)&Qg[(size_t)r * HS + 4 * c4];
            *(float4*)&Qs[r * QSTRIDE + 4 * c4] = v;
        }
    }

    float m_[4], l_[4], o[4][4];
#pragma unroll
    for (int i = 0; i < 4; i++) {
        m_[i] = -1e30f; l_[i] = 0.0f;
#pragma unroll
        for (int j = 0; j < 4; j++) o[i][j] = 0.0f;
    }

    for (int kt = 0; kt <= qt; kt++) {
        const float* Kt = Kg + (size_t)kt * 64 * HS;
        const float* Vt = Vg + (size_t)kt * 64 * HS;

        // ---- load K (transposed) and V (natural) tiles ----
        {
            int r  = tid & 63;
            int cb = tid >> 6;             // 0..3
#pragma unroll
            for (int t = 0; t < 4; t++) {
                int c4 = cb + 4 * t;
                float4 kv = *(const float4*)&Kt[(size_t)r * HS + 4 * c4];
                Kst[(4 * c4 + 0) * 64 + r] = kv.x;
                Kst[(4 * c4 + 1) * 64 + r] = kv.y;
                Kst[(4 * c4 + 2) * 64 + r] = kv.z;
                Kst[(4 * c4 + 3) * 64 + r] = kv.w;
                float4 vv = *(const float4*)&Vt[(size_t)r * HS + 4 * c4];
                *(float4*)&Vs[r * QSTRIDE + 4 * c4] = vv;
            }
        }
        __syncthreads();

        // ---- S = Q @ K^T (4x4 per thread) ----
        float s[4][4];
#pragma unroll
        for (int i = 0; i < 4; i++)
#pragma unroll
            for (int j = 0; j < 4; j++) s[i][j] = 0.0f;

#pragma unroll 8
        for (int h = 0; h < 64; h++) {
            float4 bv = *(const float4*)&Kst[h * 64 + 4 * tx];
            float a0 = Qs[(4 * ty + 0) * QSTRIDE + h];
            float a1 = Qs[(4 * ty + 1) * QSTRIDE + h];
            float a2 = Qs[(4 * ty + 2) * QSTRIDE + h];
            float a3 = Qs[(4 * ty + 3) * QSTRIDE + h];
            s[0][0] = fmaf(a0, bv.x, s[0][0]); s[0][1] = fmaf(a0, bv.y, s[0][1]);
            s[0][2] = fmaf(a0, bv.z, s[0][2]); s[0][3] = fmaf(a0, bv.w, s[0][3]);
            s[1][0] = fmaf(a1, bv.x, s[1][0]); s[1][1] = fmaf(a1, bv.y, s[1][1]);
            s[1][2] = fmaf(a1, bv.z, s[1][2]); s[1][3] = fmaf(a1, bv.w, s[1][3]);
            s[2][0] = fmaf(a2, bv.x, s[2][0]); s[2][1] = fmaf(a2, bv.y, s[2][1]);
            s[2][2] = fmaf(a2, bv.z, s[2][2]); s[2][3] = fmaf(a2, bv.w, s[2][3]);
            s[3][0] = fmaf(a3, bv.x, s[3][0]); s[3][1] = fmaf(a3, bv.y, s[3][1]);
            s[3][2] = fmaf(a3, bv.z, s[3][2]); s[3][3] = fmaf(a3, bv.w, s[3][3]);
        }

        // ---- causal mask on the diagonal tile ----
        if (kt == qt) {
#pragma unroll
            for (int i = 0; i < 4; i++)
#pragma unroll
                for (int j = 0; j < 4; j++)
                    if (4 * tx + j > 4 * ty + i) s[i][j] = -1e30f;
        }

        // ---- online softmax (rows reduced across the 16 tx lanes) ----
        float tmax[4], psum[4], alpha[4];
#pragma unroll
        for (int i = 0; i < 4; i++) {
            float mx = fmaxf(fmaxf(s[i][0], s[i][1]), fmaxf(s[i][2], s[i][3]));
#pragma unroll
            for (int off = 1; off < 16; off <<= 1)
                mx = fmaxf(mx, __shfl_xor_sync(0xffffffffu, mx, off));
            tmax[i] = mx;
        }
#pragma unroll
        for (int i = 0; i < 4; i++) {
            float mnew = fmaxf(m_[i], tmax[i]);
            alpha[i] = __expf(m_[i] - mnew);
            m_[i] = mnew;
            float ps = 0.0f;
#pragma unroll
            for (int j = 0; j < 4; j++) {
                s[i][j] = __expf(s[i][j] - mnew);
                ps += s[i][j];
            }
#pragma unroll
            for (int off = 1; off < 16; off <<= 1)
                ps += __shfl_xor_sync(0xffffffffu, ps, off);
            psum[i] = ps;
            l_[i] = l_[i] * alpha[i] + psum[i];
#pragma unroll
            for (int j = 0; j < 4; j++) o[i][j] *= alpha[i];
        }

        // ---- publish P tile ----
#pragma unroll
        for (int i = 0; i < 4; i++) {
            float4 pv = make_float4(s[i][0], s[i][1], s[i][2], s[i][3]);
            *(float4*)&Ps[(4 * ty + i) * QSTRIDE + 4 * tx] = pv;
        }
        __syncthreads();

        // ---- O += P @ V ----
#pragma unroll 8
        for (int j = 0; j < 64; j++) {
            float4 vv = *(const float4*)&Vs[j * QSTRIDE + 4 * tx];
            float p0 = Ps[(4 * ty + 0) * QSTRIDE + j];
            float p1 = Ps[(4 * ty + 1) * QSTRIDE + j];
            float p2 = Ps[(4 * ty + 2) * QSTRIDE + j];
            float p3 = Ps[(4 * ty + 3) * QSTRIDE + j];
            o[0][0] = fmaf(p0, vv.x, o[0][0]); o[0][1] = fmaf(p0, vv.y, o[0][1]);
            o[0][2] = fmaf(p0, vv.z, o[0][2]); o[0][3] = fmaf(p0, vv.w, o[0][3]);
            o[1][0] = fmaf(p1, vv.x, o[1][0]); o[1][1] = fmaf(p1, vv.y, o[1][1]);
            o[1][2] = fmaf(p1, vv.z, o[1][2]); o[1][3] = fmaf(p1, vv.w, o[1][3]);
            o[2][0] = fmaf(p2, vv.x, o[2][0]); o[2][1] = fmaf(p2, vv.y, o[2][1]);
            o[2][2] = fmaf(p2, vv.z, o[2][2]); o[2][3] = fmaf(p2, vv.w, o[2][3]);
            o[3][0] = fmaf(p3, vv.x, o[3][0]); o[3][1] = fmaf(p3, vv.y, o[3][1]);
            o[3][2] = fmaf(p3, vv.z, o[3][2]); o[3][3] = fmaf(p3, vv.w, o[3][3]);
        }
        __syncthreads();
    }

    // ---- epilogue: divide by row-sum AND by sqrt(HS)=8 (the reference quirk:
    // softmax first, then /sqrt(head_size), applied post-PV since it's linear) ----
#pragma unroll
    for (int i = 0; i < 4; i++) {
        float inv = 1.0f / (l_[i] * 8.0f);
        float4 ov = make_float4(o[i][0] * inv, o[i][1] * inv, o[i][2] * inv, o[i][3] * inv);
        size_t row = (size_t)b * TSEQ + qt * 64 + 4 * ty + i;
        *(float4*)&out[row * HS + 4 * tx] = ov;
    }
}

// ---------------------------------------------------------------------------
extern "C" void kernel_launch(void* const* d_in, const int* in_sizes, int n_in,
                              void* d_out, int out_size)
{
    const float* X  = (const float*)d_in[0];
    const float* Wq = (const float*)d_in[1];
    const float* Wk = (const float*)d_in[2];
    const float* Wv = (const float*)d_in[3];
    float* out = (float*)d_out;

    (void)in_sizes; (void)n_in; (void)out_size;

    // QKV projection: grid (16384/128, 3)
    dim3 g1(MTOT / 128, 3);
    qkv_kernel<<<g1, 256>>>(X, Wq, Wk, Wv);

    // Flash attention: grid (64 q-tiles, 4 batches), 67 KB dynamic smem
    cudaFuncSetAttribute(attn_kernel, cudaFuncAttributeMaxDynamicSharedMemorySize, SMEM_BYTES);
    dim3 g2(64, BATCH);
    attn_kernel<<<g2, 256, SMEM_BYTES>>>(out);
}